// round 16
// baseline (speedup 1.0000x reference)
#include <cuda_runtime.h>
#include <cstdint>

#define B_   2
#define N_   8192
#define FIN_ 128
#define FO_  64

// q,k: [b][tok][feat] tf32; v: TRANSPOSED [b][feat][tok] tf32 with tokens
// PERMUTED within each 8-group: position j holds tok (j<4 ? 2j : 2(j-4)+1),
// so a plain ldmatrix yields B-fragments whose k-slots match the S-accumulator
// C-fragment layout (register-direct P, no smem round-trip).
__device__ __align__(16) uint32_t g_qkv[3][(size_t)B_ * N_ * FO_];

// split-KV partials: O unnormalized (common 2^-32 scale), l per row
#define SPLITS 4
__device__ __align__(16) float g_pO[(size_t)SPLITS * B_ * N_ * FO_];
__device__ float g_pL[SPLITS * B_ * N_];

__device__ __forceinline__ uint32_t f2tf(float x) {
    uint32_t r;
    asm("cvt.rna.tf32.f32 %0, %1;" : "=r"(r) : "f"(x));
    return r;
}
__device__ __forceinline__ float ex2(float x) {
    float r;
    asm("ex2.approx.f32 %0, %1;" : "=f"(r) : "f"(x));
    return r;
}

__device__ __forceinline__ void mma8(float c[4], const uint32_t a[4],
                                     uint32_t b0, uint32_t b1) {
    asm("mma.sync.aligned.m16n8k8.row.col.f32.tf32.tf32.f32 "
        "{%0,%1,%2,%3}, {%4,%5,%6,%7}, {%8,%9}, {%0,%1,%2,%3};\n"
        : "+f"(c[0]), "+f"(c[1]), "+f"(c[2]), "+f"(c[3])
        : "r"(a[0]), "r"(a[1]), "r"(a[2]), "r"(a[3]), "r"(b0), "r"(b1));
}

__device__ __forceinline__ void ldsm4(uint32_t& r0, uint32_t& r1,
                                      uint32_t& r2, uint32_t& r3, uint32_t a) {
    asm volatile("ldmatrix.sync.aligned.m8n8.x4.shared.b16 {%0,%1,%2,%3}, [%4];"
                 : "=r"(r0), "=r"(r1), "=r"(r2), "=r"(r3) : "r"(a));
}

__device__ __forceinline__ void cp16(uint32_t dst, const void* src) {
    asm volatile("cp.async.cg.shared.global [%0], [%1], 16;\n"
                 :: "r"(dst), "l"(src));
}
__device__ __forceinline__ void cp_commit() {
    asm volatile("cp.async.commit_group;\n" ::: "memory");
}
__device__ __forceinline__ void cp_wait0() {
    asm volatile("cp.async.wait_group 0;\n" ::: "memory");
}

// ---------------------------------------------------------------------------
// Kernel 1: fused 2-layer MLP (q/k/v selected by blockIdx.y), 64 rows/block.
// Feature tile loaded raw via cp.async (cvt in A-frag loads). Hs aliases Xs.
// k pre-scaled by log2(e); v transposed [feat][tok] with permuted tok groups.
// ---------------------------------------------------------------------------
#define LX 136
#define LW 72

__global__ void __launch_bounds__(128, 2)
mlp_kernel(const float* __restrict__ feature,
           const float* __restrict__ Wa0, const float* __restrict__ ba0,
           const float* __restrict__ Wb0, const float* __restrict__ bb0,
           const float* __restrict__ Wa1, const float* __restrict__ ba1,
           const float* __restrict__ Wb1, const float* __restrict__ bb1,
           const float* __restrict__ Wa2, const float* __restrict__ ba2,
           const float* __restrict__ Wb2, const float* __restrict__ bb2)
{
    extern __shared__ uint32_t sm_[];
    uint32_t* Xs  = sm_;                  // 64 x LX (raw fp32 X; reused as Hs)
    uint32_t* W1s = Xs + 64 * LX;         // 128 x LW (tf32)
    uint32_t* W2s = W1s + 128 * LW;       // 64 x LW (tf32)
    uint32_t* Hs  = Xs;                   // ALIAS

    const int which = blockIdx.y;
    const float* Wa = which == 0 ? Wa0 : which == 1 ? Wa1 : Wa2;
    const float* ba = which == 0 ? ba0 : which == 1 ? ba1 : ba2;
    const float* Wb = which == 0 ? Wb0 : which == 1 ? Wb1 : Wb2;
    const float* bb = which == 0 ? bb0 : which == 1 ? bb1 : bb2;
    const float osc = (which == 1) ? 1.4426950408889634f : 1.0f;

    const int tid  = threadIdx.x;
    const int row0 = blockIdx.x * 64;

    {
        // X: async raw fp32 (fire-and-forget, overlaps weight loads)
        uint32_t xbase = (uint32_t)__cvta_generic_to_shared(Xs);
        const float4* f4 = (const float4*)(feature + (size_t)row0 * FIN_);
        for (int i = tid; i < 64 * (FIN_ / 4); i += 128)
            cp16(xbase + (uint32_t)((((i >> 5) * LX) + ((i & 31) << 2)) * 4), f4 + i);
        cp_commit();

        const float4* w4 = (const float4*)Wa;     // 128 x 64
        for (int i = tid; i < FIN_ * (FO_ / 4); i += 128) {
            float4 v = w4[i];
            uint32_t* d = W1s + (i >> 4) * LW + ((i & 15) << 2);
            d[0] = f2tf(v.x); d[1] = f2tf(v.y); d[2] = f2tf(v.z); d[3] = f2tf(v.w);
        }
        const float4* w24 = (const float4*)Wb;    // 64 x 64
        for (int i = tid; i < FO_ * (FO_ / 4); i += 128) {
            float4 v = w24[i];
            uint32_t* d = W2s + (i >> 4) * LW + ((i & 15) << 2);
            d[0] = f2tf(v.x); d[1] = f2tf(v.y); d[2] = f2tf(v.z); d[3] = f2tf(v.w);
        }
        cp_wait0();
    }
    __syncthreads();

    const int lane = tid & 31, warp = tid >> 5;
    const int gid = lane >> 2, tig = lane & 3;
    const int rw = warp * 16;

    float C[8][4];
#pragma unroll
    for (int nt = 0; nt < 8; nt++) { C[nt][0] = C[nt][1] = C[nt][2] = C[nt][3] = 0.f; }

#pragma unroll
    for (int kc = 0; kc < 16; kc++) {
        uint32_t a[4];
        const float* Ar = (const float*)Xs + (rw + gid) * LX + kc * 8 + tig;
        a[0] = f2tf(Ar[0]); a[2] = f2tf(Ar[4]);
        a[1] = f2tf(Ar[8 * LX]); a[3] = f2tf(Ar[8 * LX + 4]);
#pragma unroll
        for (int nt = 0; nt < 8; nt++) {
            const uint32_t* Br = W1s + (kc * 8 + tig) * LW + nt * 8 + gid;
            mma8(C[nt], a, Br[0], Br[4 * LW]);
        }
    }
    __syncthreads();      // everyone done reading Xs before Hs overwrites it
#pragma unroll
    for (int nt = 0; nt < 8; nt++) {
        int col = nt * 8 + 2 * tig;
        float bx = ba[col], by = ba[col + 1];
        Hs[(rw + gid) * LW + col]         = f2tf(fmaxf(C[nt][0] + bx, 0.f));
        Hs[(rw + gid) * LW + col + 1]     = f2tf(fmaxf(C[nt][1] + by, 0.f));
        Hs[(rw + gid + 8) * LW + col]     = f2tf(fmaxf(C[nt][2] + bx, 0.f));
        Hs[(rw + gid + 8) * LW + col + 1] = f2tf(fmaxf(C[nt][3] + by, 0.f));
    }
    __syncwarp();         // Hs rows are warp-private

#pragma unroll
    for (int nt = 0; nt < 8; nt++) { C[nt][0] = C[nt][1] = C[nt][2] = C[nt][3] = 0.f; }
#pragma unroll
    for (int kc = 0; kc < 8; kc++) {
        uint32_t a[4];
        const uint32_t* Ar = Hs + (rw + gid) * LW + kc * 8 + tig;
        a[0] = Ar[0]; a[2] = Ar[4]; a[1] = Ar[8 * LW]; a[3] = Ar[8 * LW + 4];
#pragma unroll
        for (int nt = 0; nt < 8; nt++) {
            const uint32_t* Br = W2s + (kc * 8 + tig) * LW + nt * 8 + gid;
            mma8(C[nt], a, Br[0], Br[4 * LW]);
        }
    }
    if (which == 2) {
        // v: write transposed vt[b][feat][tok] with PERMUTED token position:
        // tok t -> group_base + (t&1)*4 + ((t&7)>>1)
        const int t  = row0 + rw + gid;
        const int bt = t >> 13, tk = t & (N_ - 1);
        const int tkp = tk - gid + ((gid & 1) << 2) + (gid >> 1);
        uint32_t* vt = g_qkv[2] + (size_t)bt * FO_ * N_ + tkp;
#pragma unroll
        for (int nt = 0; nt < 8; nt++) {
            int col = nt * 8 + 2 * tig;
            float bx = bb[col], by = bb[col + 1];
            vt[(size_t)col * N_]           = f2tf(fmaxf(C[nt][0] + bx, 0.f));
            vt[(size_t)(col + 1) * N_]     = f2tf(fmaxf(C[nt][1] + by, 0.f));
            vt[(size_t)col * N_ + 8]       = f2tf(fmaxf(C[nt][2] + bx, 0.f));
            vt[(size_t)(col + 1) * N_ + 8] = f2tf(fmaxf(C[nt][3] + by, 0.f));
        }
    } else {
        uint32_t* outp = g_qkv[which];
#pragma unroll
        for (int nt = 0; nt < 8; nt++) {
            int col = nt * 8 + 2 * tig;
            float bx = bb[col], by = bb[col + 1];
            uint2 o0 = make_uint2(f2tf(fmaxf(C[nt][0] + bx, 0.f) * osc),
                                  f2tf(fmaxf(C[nt][1] + by, 0.f) * osc));
            uint2 o1 = make_uint2(f2tf(fmaxf(C[nt][2] + bx, 0.f) * osc),
                                  f2tf(fmaxf(C[nt][3] + by, 0.f) * osc));
            *(uint2*)(outp + (size_t)(row0 + rw + gid) * FO_ + col)     = o0;
            *(uint2*)(outp + (size_t)(row0 + rw + gid + 8) * FO_ + col) = o1;
        }
    }
}

// ---------------------------------------------------------------------------
// Kernel 2: flash attention, split-KV x4, NO-MAX softmax, REGISTER-DIRECT P.
// BM=64, BN=32, 4 warps (m16 x n32 each), 4 CTAs/SM.
// ---------------------------------------------------------------------------
#define LK  68   // K tile stride (64 feat cols + pad)
#define LVT 36   // Vt tile stride (32 tok cols + pad)
#define LP  36   // x_weight tile stride (32 cols + pad)
#define BM 64
#define BN 32
#define KVLEN (N_ / SPLITS)     // 2048
#define NIT   (KVLEN / BN)      // 64

__global__ void __launch_bounds__(128, 4)
attn_kernel(const float* __restrict__ xw)
{
    extern __shared__ uint32_t sm_[];
    uint32_t* KsB = sm_;                            // 2 x 32 x LK  (also Q staging)
    uint32_t* VsB = KsB + 2 * BN * LK;              // 2 x 64 x LVT
    uint32_t* WsB = VsB + 2 * 64 * LVT;             // 2 x 64 x LP (fp32 W)

    const int b   = blockIdx.y;
    const int sp  = blockIdx.z;
    const int q0  = blockIdx.x * BM;
    const int kvb = sp * KVLEN;
    const int tid = threadIdx.x, lane = tid & 31, warp = tid >> 5;
    const int gid = lane >> 2, tig = lane & 3;
    const int rw  = warp * 16;

    const uint32_t* qb  = g_qkv[0] + (size_t)b * N_ * FO_;
    const uint32_t* kb  = g_qkv[1] + (size_t)b * N_ * FO_;
    const uint32_t* vtb = g_qkv[2] + (size_t)b * FO_ * N_;   // [feat][tok-permuted]
    const float*    wb  = xw + (size_t)b * N_ * N_;

    const uint32_t KsA0 = (uint32_t)__cvta_generic_to_shared(KsB);
    const uint32_t VsA0 = (uint32_t)__cvta_generic_to_shared(VsB);
    const uint32_t WsA0 = (uint32_t)__cvta_generic_to_shared(WsB);

    // ldmatrix lane mapping (rows = n-dim, cols = k-dim)
    const int row_  = ((lane >> 4) << 3) + (lane & 7);
    const int half_ = ((lane >> 3) & 1) << 2;

    // ---- stage Q (64 x 64) through the K double-buffer ----
    {
        const uint4* q4 = (const uint4*)(qb + (size_t)q0 * FO_);
        for (int i = tid; i < BM * (FO_ / 4); i += 128) {
            uint4 v = q4[i];
            uint32_t* d = KsB + (i >> 4) * LK + ((i & 15) << 2);
            d[0] = v.x; d[1] = v.y; d[2] = v.z; d[3] = v.w;
        }
    }
    __syncthreads();
    uint32_t Qa[8][4];
#pragma unroll
    for (int kc = 0; kc < 8; kc++) {
        const uint32_t* Ar = KsB + (rw + gid) * LK + kc * 8 + tig;
        Qa[kc][0] = Ar[0]; Qa[kc][2] = Ar[4];
        Qa[kc][1] = Ar[8 * LK]; Qa[kc][3] = Ar[8 * LK + 4];
    }
    __syncthreads();

    auto issue_loads = [&](int it, int buf) {
        const int kv0 = kvb + it * BN;
        uint32_t kbase = KsA0 + (uint32_t)(buf * BN * LK * 4);
        uint32_t vbase = VsA0 + (uint32_t)(buf * 64 * LVT * 4);
        uint32_t wbase = WsA0 + (uint32_t)(buf * BM * LP * 4);
        const uint32_t* ksrc = kb + (size_t)kv0 * FO_;
        const uint32_t* vsrc = vtb + kv0;                    // row stride N_
        const float*    wsrc = wb + (size_t)q0 * N_ + kv0;
#pragma unroll
        for (int j = 0; j < 4; j++) {              // 512 16B chunks per array
            int i = tid + 128 * j;
            {   // K: 32 rows x 16 chunks
                int r = i >> 4, c = (i & 15) << 2;
                cp16(kbase + (uint32_t)((r * LK + c) * 4), ksrc + r * FO_ + c);
            }
            {   // Vt: 64 rows x 8 chunks
                int r = i >> 3, c = (i & 7) << 2;
                cp16(vbase + (uint32_t)((r * LVT + c) * 4), vsrc + (size_t)r * N_ + c);
            }
            {   // W: 64 rows x 8 chunks
                int r = i >> 3, c = (i & 7) << 2;
                cp16(wbase + (uint32_t)((r * LP + c) * 4), wsrc + (size_t)r * N_ + c);
            }
        }
    };

    float Oc[8][4];
#pragma unroll
    for (int nt = 0; nt < 8; nt++) { Oc[nt][0] = Oc[nt][1] = Oc[nt][2] = Oc[nt][3] = 0.f; }
    float l0 = 0.f, l1 = 0.f;   // per-thread partial row sums (2^-32-scaled)

    issue_loads(0, 0);
    cp_commit();

    for (int it = 0; it < NIT; it++) {
        const int buf = it & 1;
        cp_wait0();
        __syncthreads();   // chunks arrived; all warps finished iter it-1

        // prefetch next tiles NOW: buf^1 is provably consumed (barrier above)
        if (it + 1 < NIT) { issue_loads(it + 1, buf ^ 1); cp_commit(); }

        const uint32_t KsA = KsA0 + (uint32_t)(buf * BN * LK * 4);
        const uint32_t VsA = VsA0 + (uint32_t)(buf * 64 * LVT * 4);
        const float*   Wf  = (const float*)(WsB + buf * BM * LP);

        // ---- S = Q @ K^T : 16 rows x 32 cols, kc over 8 feat chunks ----
        float S[4][4];
#pragma unroll
        for (int nt = 0; nt < 4; nt++) { S[nt][0] = S[nt][1] = S[nt][2] = S[nt][3] = 0.f; }
#pragma unroll
        for (int kc = 0; kc < 8; kc++) {
            uint32_t bk[2][4];
#pragma unroll
            for (int ntp = 0; ntp < 2; ntp++)
                ldsm4(bk[ntp][0], bk[ntp][1], bk[ntp][2], bk[ntp][3],
                      KsA + (uint32_t)((((ntp * 16 + row_) * LK) + kc * 8 + half_) * 4));
#pragma unroll
            for (int ntp = 0; ntp < 2; ntp++) {
                mma8(S[2 * ntp],     Qa[kc], bk[ntp][0], bk[ntp][1]);
                mma8(S[2 * ntp + 1], Qa[kc], bk[ntp][2], bk[ntp][3]);
            }
        }

        // ---- softmax: p = 2^(max(s*w-32,-32)), P stays in REGISTERS as
        //      A-fragments (order a = {p0, p2, p1, p3} matches C-layout) ----
        uint32_t Pa[4][4];
#pragma unroll
        for (int nt = 0; nt < 4; nt++) {
            const float2 wA = *(const float2*)(Wf + (rw + gid) * LP + nt * 8 + 2 * tig);
            const float2 wB = *(const float2*)(Wf + (rw + gid + 8) * LP + nt * 8 + 2 * tig);
            float p0 = ex2(fmaxf(fmaf(S[nt][0], wA.x, -32.f), -32.f));
            float p1 = ex2(fmaxf(fmaf(S[nt][1], wA.y, -32.f), -32.f));
            float p2 = ex2(fmaxf(fmaf(S[nt][2], wB.x, -32.f), -32.f));
            float p3 = ex2(fmaxf(fmaf(S[nt][3], wB.y, -32.f), -32.f));
            l0 += p0 + p1; l1 += p2 + p3;
            Pa[nt][0] = f2tf(p0); Pa[nt][1] = f2tf(p2);
            Pa[nt][2] = f2tf(p1); Pa[nt][3] = f2tf(p3);
        }

        // ---- O += P @ V : kc = the 4 S n-tiles (8 toks each, permuted Vt) ----
#pragma unroll
        for (int kc = 0; kc < 4; kc++) {
            uint32_t bv[4][4];
#pragma unroll
            for (int ntp = 0; ntp < 4; ntp++)
                ldsm4(bv[ntp][0], bv[ntp][1], bv[ntp][2], bv[ntp][3],
                      VsA + (uint32_t)((((ntp * 16 + row_) * LVT) + kc * 8 + half_) * 4));
#pragma unroll
            for (int ntp = 0; ntp < 4; ntp++) {
                mma8(Oc[2 * ntp],     Pa[kc], bv[ntp][0], bv[ntp][1]);
                mma8(Oc[2 * ntp + 1], Pa[kc], bv[ntp][2], bv[ntp][3]);
            }
        }
    }

    // ---- final l reduction across the quad, store partials ----
    l0 += __shfl_xor_sync(0xffffffffu, l0, 1);
    l0 += __shfl_xor_sync(0xffffffffu, l0, 2);
    l1 += __shfl_xor_sync(0xffffffffu, l1, 1);
    l1 += __shfl_xor_sync(0xffffffffu, l1, 2);

    float* pO = g_pO + ((size_t)(sp * B_ + b) * N_ + q0) * FO_;
#pragma unroll
    for (int nt = 0; nt < 8; nt++) {
        int col = nt * 8 + 2 * tig;
        *(float2*)(pO + (size_t)(rw + gid) * FO_ + col) =
            make_float2(Oc[nt][0], Oc[nt][1]);
        *(float2*)(pO + (size_t)(rw + gid + 8) * FO_ + col) =
            make_float2(Oc[nt][2], Oc[nt][3]);
    }
    if (tig == 0) {
        int idx = (sp * B_ + b) * N_ + q0 + rw + gid;
        g_pL[idx] = l0;
        g_pL[idx + 8] = l1;
    }
}

// ---------------------------------------------------------------------------
// Kernel 3: merge the 4 split-KV partials (common scale), normalize, relu
// ---------------------------------------------------------------------------
__global__ void __launch_bounds__(256)
combine_kernel(float* __restrict__ out)
{
    const int idx = blockIdx.x * 256 + threadIdx.x;   // B_*N_*16 float4 slots
    const int row = idx >> 4;
    const int c4  = (idx & 15) << 2;

    float lsum = 0.f;
#pragma unroll
    for (int s = 0; s < SPLITS; s++) lsum += g_pL[s * B_ * N_ + row];
    const float inv = 1.f / lsum;

    float4 acc = make_float4(0.f, 0.f, 0.f, 0.f);
#pragma unroll
    for (int s = 0; s < SPLITS; s++) {
        const float4 o = *(const float4*)(g_pO + ((size_t)s * B_ * N_ + row) * FO_ + c4);
        acc.x += o.x; acc.y += o.y; acc.z += o.z; acc.w += o.w;
    }
    float4 r;
    r.x = fmaxf(acc.x * inv, 0.f);
    r.y = fmaxf(acc.y * inv, 0.f);
    r.z = fmaxf(acc.z * inv, 0.f);
    r.w = fmaxf(acc.w * inv, 0.f);
    *(float4*)(out + (size_t)row * FO_ + c4) = r;
}

// ---------------------------------------------------------------------------
extern "C" void kernel_launch(void* const* d_in, const int* in_sizes, int n_in,
                              void* d_out, int out_size)
{
    const float* feature = (const float*)d_in[0];
    const float* xw      = (const float*)d_in[1];
    const float* W11 = (const float*)d_in[2],  *b11 = (const float*)d_in[3];
    const float* W12 = (const float*)d_in[4],  *b12 = (const float*)d_in[5];
    const float* W21 = (const float*)d_in[6],  *b21 = (const float*)d_in[7];
    const float* W22 = (const float*)d_in[8],  *b22 = (const float*)d_in[9];
    const float* W31 = (const float*)d_in[10], *b31 = (const float*)d_in[11];
    const float* W32 = (const float*)d_in[12], *b32 = (const float*)d_in[13];

    const int mlp_smem  = (64 * LX + 128 * LW + 64 * LW) * 4;               // 90112
    const int attn_smem = (2 * BN * LK + 2 * 64 * LVT + 2 * BM * LP) * 4;   // 54272
    cudaFuncSetAttribute(mlp_kernel,  cudaFuncAttributeMaxDynamicSharedMemorySize, mlp_smem);
    cudaFuncSetAttribute(attn_kernel, cudaFuncAttributeMaxDynamicSharedMemorySize, attn_smem);

    mlp_kernel<<<dim3((B_ * N_) / 64, 3), 128, mlp_smem>>>(
        feature, W11, b11, W12, b12, W21, b21, W22, b22, W31, b31, W32, b32);

    attn_kernel<<<dim3(N_ / BM, B_, SPLITS), 128, attn_smem>>>(xw);

    combine_kernel<<<(B_ * N_ * 16) / 256, 256>>>((float*)d_out);
}

// round 17
// speedup vs baseline: 1.3912x; 1.3912x over previous
#include <cuda_runtime.h>
#include <cstdint>

#define B_   2
#define N_   8192
#define FIN_ 128
#define FO_  64

// q,k: [b][tok][feat] tf32; v: TRANSPOSED [b][feat][tok] tf32
__device__ __align__(16) uint32_t g_qkv[3][(size_t)B_ * N_ * FO_];

// split-KV partials: O unnormalized (common 2^-32 scale), l per row
#define SPLITS 4
__device__ __align__(16) float g_pO[(size_t)SPLITS * B_ * N_ * FO_];
__device__ float g_pL[SPLITS * B_ * N_];

__device__ __forceinline__ uint32_t f2tf(float x) {
    uint32_t r;
    asm("cvt.rna.tf32.f32 %0, %1;" : "=r"(r) : "f"(x));
    return r;
}
__device__ __forceinline__ float ex2(float x) {
    float r;
    asm("ex2.approx.f32 %0, %1;" : "=f"(r) : "f"(x));
    return r;
}

__device__ __forceinline__ void mma8(float c[4], const uint32_t a[4],
                                     uint32_t b0, uint32_t b1) {
    asm("mma.sync.aligned.m16n8k8.row.col.f32.tf32.tf32.f32 "
        "{%0,%1,%2,%3}, {%4,%5,%6,%7}, {%8,%9}, {%0,%1,%2,%3};\n"
        : "+f"(c[0]), "+f"(c[1]), "+f"(c[2]), "+f"(c[3])
        : "r"(a[0]), "r"(a[1]), "r"(a[2]), "r"(a[3]), "r"(b0), "r"(b1));
}

__device__ __forceinline__ void ldsm4(uint32_t& r0, uint32_t& r1,
                                      uint32_t& r2, uint32_t& r3, uint32_t a) {
    asm volatile("ldmatrix.sync.aligned.m8n8.x4.shared.b16 {%0,%1,%2,%3}, [%4];"
                 : "=r"(r0), "=r"(r1), "=r"(r2), "=r"(r3) : "r"(a));
}

__device__ __forceinline__ void cp16(uint32_t dst, const void* src) {
    asm volatile("cp.async.cg.shared.global [%0], [%1], 16;\n"
                 :: "r"(dst), "l"(src));
}
__device__ __forceinline__ void cp_commit() {
    asm volatile("cp.async.commit_group;\n" ::: "memory");
}
__device__ __forceinline__ void cp_wait0() {
    asm volatile("cp.async.wait_group 0;\n" ::: "memory");
}

// ---------------------------------------------------------------------------
// Kernel 1: fused 2-layer MLP (q/k/v selected by blockIdx.y), 64 rows/block.
// Feature tile loaded raw via cp.async (cvt in A-frag loads). Hs aliases Xs.
// k pre-scaled by log2(e); v transposed [feat][tok].     [R14 proven version]
// ---------------------------------------------------------------------------
#define LX 136
#define LW 72

__global__ void __launch_bounds__(128, 2)
mlp_kernel(const float* __restrict__ feature,
           const float* __restrict__ Wa0, const float* __restrict__ ba0,
           const float* __restrict__ Wb0, const float* __restrict__ bb0,
           const float* __restrict__ Wa1, const float* __restrict__ ba1,
           const float* __restrict__ Wb1, const float* __restrict__ bb1,
           const float* __restrict__ Wa2, const float* __restrict__ ba2,
           const float* __restrict__ Wb2, const float* __restrict__ bb2)
{
    extern __shared__ uint32_t sm_[];
    uint32_t* Xs  = sm_;                  // 64 x LX (raw fp32 X; reused as Hs)
    uint32_t* W1s = Xs + 64 * LX;         // 128 x LW (tf32)
    uint32_t* W2s = W1s + 128 * LW;       // 64 x LW (tf32)
    uint32_t* Hs  = Xs;                   // ALIAS

    const int which = blockIdx.y;
    const float* Wa = which == 0 ? Wa0 : which == 1 ? Wa1 : Wa2;
    const float* ba = which == 0 ? ba0 : which == 1 ? ba1 : ba2;
    const float* Wb = which == 0 ? Wb0 : which == 1 ? Wb1 : Wb2;
    const float* bb = which == 0 ? bb0 : which == 1 ? bb1 : bb2;
    const float osc = (which == 1) ? 1.4426950408889634f : 1.0f;

    const int tid  = threadIdx.x;
    const int row0 = blockIdx.x * 64;

    {
        // X: async raw fp32 (fire-and-forget, overlaps weight loads)
        uint32_t xbase = (uint32_t)__cvta_generic_to_shared(Xs);
        const float4* f4 = (const float4*)(feature + (size_t)row0 * FIN_);
        for (int i = tid; i < 64 * (FIN_ / 4); i += 128)
            cp16(xbase + (uint32_t)((((i >> 5) * LX) + ((i & 31) << 2)) * 4), f4 + i);
        cp_commit();

        const float4* w4 = (const float4*)Wa;     // 128 x 64
        for (int i = tid; i < FIN_ * (FO_ / 4); i += 128) {
            float4 v = w4[i];
            uint32_t* d = W1s + (i >> 4) * LW + ((i & 15) << 2);
            d[0] = f2tf(v.x); d[1] = f2tf(v.y); d[2] = f2tf(v.z); d[3] = f2tf(v.w);
        }
        const float4* w24 = (const float4*)Wb;    // 64 x 64
        for (int i = tid; i < FO_ * (FO_ / 4); i += 128) {
            float4 v = w24[i];
            uint32_t* d = W2s + (i >> 4) * LW + ((i & 15) << 2);
            d[0] = f2tf(v.x); d[1] = f2tf(v.y); d[2] = f2tf(v.z); d[3] = f2tf(v.w);
        }
        cp_wait0();
    }
    __syncthreads();

    const int lane = tid & 31, warp = tid >> 5;
    const int gid = lane >> 2, tig = lane & 3;
    const int rw = warp * 16;

    float C[8][4];
#pragma unroll
    for (int nt = 0; nt < 8; nt++) { C[nt][0] = C[nt][1] = C[nt][2] = C[nt][3] = 0.f; }

#pragma unroll
    for (int kc = 0; kc < 16; kc++) {
        uint32_t a[4];
        const float* Ar = (const float*)Xs + (rw + gid) * LX + kc * 8 + tig;
        a[0] = f2tf(Ar[0]); a[2] = f2tf(Ar[4]);
        a[1] = f2tf(Ar[8 * LX]); a[3] = f2tf(Ar[8 * LX + 4]);
#pragma unroll
        for (int nt = 0; nt < 8; nt++) {
            const uint32_t* Br = W1s + (kc * 8 + tig) * LW + nt * 8 + gid;
            mma8(C[nt], a, Br[0], Br[4 * LW]);
        }
    }
    __syncthreads();      // everyone done reading Xs before Hs overwrites it
#pragma unroll
    for (int nt = 0; nt < 8; nt++) {
        int col = nt * 8 + 2 * tig;
        float bx = ba[col], by = ba[col + 1];
        Hs[(rw + gid) * LW + col]         = f2tf(fmaxf(C[nt][0] + bx, 0.f));
        Hs[(rw + gid) * LW + col + 1]     = f2tf(fmaxf(C[nt][1] + by, 0.f));
        Hs[(rw + gid + 8) * LW + col]     = f2tf(fmaxf(C[nt][2] + bx, 0.f));
        Hs[(rw + gid + 8) * LW + col + 1] = f2tf(fmaxf(C[nt][3] + by, 0.f));
    }
    __syncwarp();         // Hs rows are warp-private

#pragma unroll
    for (int nt = 0; nt < 8; nt++) { C[nt][0] = C[nt][1] = C[nt][2] = C[nt][3] = 0.f; }
#pragma unroll
    for (int kc = 0; kc < 8; kc++) {
        uint32_t a[4];
        const uint32_t* Ar = Hs + (rw + gid) * LW + kc * 8 + tig;
        a[0] = Ar[0]; a[2] = Ar[4]; a[1] = Ar[8 * LW]; a[3] = Ar[8 * LW + 4];
#pragma unroll
        for (int nt = 0; nt < 8; nt++) {
            const uint32_t* Br = W2s + (kc * 8 + tig) * LW + nt * 8 + gid;
            mma8(C[nt], a, Br[0], Br[4 * LW]);
        }
    }
    if (which == 2) {
        // v: write transposed vt[b][feat][tok]
        const int t  = row0 + rw + gid;
        const int bt = t >> 13, tk = t & (N_ - 1);
        uint32_t* vt = g_qkv[2] + (size_t)bt * FO_ * N_ + tk;
#pragma unroll
        for (int nt = 0; nt < 8; nt++) {
            int col = nt * 8 + 2 * tig;
            float bx = bb[col], by = bb[col + 1];
            vt[(size_t)col * N_]           = f2tf(fmaxf(C[nt][0] + bx, 0.f));
            vt[(size_t)(col + 1) * N_]     = f2tf(fmaxf(C[nt][1] + by, 0.f));
            vt[(size_t)col * N_ + 8]       = f2tf(fmaxf(C[nt][2] + bx, 0.f));
            vt[(size_t)(col + 1) * N_ + 8] = f2tf(fmaxf(C[nt][3] + by, 0.f));
        }
    } else {
        uint32_t* outp = g_qkv[which];
#pragma unroll
        for (int nt = 0; nt < 8; nt++) {
            int col = nt * 8 + 2 * tig;
            float bx = bb[col], by = bb[col + 1];
            uint2 o0 = make_uint2(f2tf(fmaxf(C[nt][0] + bx, 0.f) * osc),
                                  f2tf(fmaxf(C[nt][1] + by, 0.f) * osc));
            uint2 o1 = make_uint2(f2tf(fmaxf(C[nt][2] + bx, 0.f) * osc),
                                  f2tf(fmaxf(C[nt][3] + by, 0.f) * osc));
            *(uint2*)(outp + (size_t)(row0 + rw + gid) * FO_ + col)     = o0;
            *(uint2*)(outp + (size_t)(row0 + rw + gid + 8) * FO_ + col) = o1;
        }
    }
}

// ---------------------------------------------------------------------------
// Kernel 2: flash attention, split-KV x4, NO-MAX softmax (fixed 2^-32 scale).
// BM=64, BN=32, 4 warps (m16 x n32 each), 4 CTAs/SM.     [R14 + FFMA fold]
// ---------------------------------------------------------------------------
#define LK  68   // K tile stride (64 feat cols + pad)
#define LVT 36   // Vt tile stride (32 tok cols + pad)
#define LP  36   // x_weight / P tile stride (32 cols + pad)
#define BM 64
#define BN 32
#define KVLEN (N_ / SPLITS)     // 2048
#define NIT   (KVLEN / BN)      // 64

__global__ void __launch_bounds__(128, 4)
attn_kernel(const float* __restrict__ xw)
{
    extern __shared__ uint32_t sm_[];
    uint32_t* KsB = sm_;                            // 2 x 32 x LK  (also Q staging)
    uint32_t* VsB = KsB + 2 * BN * LK;              // 2 x 64 x LVT
    uint32_t* WsB = VsB + 2 * 64 * LVT;             // 2 x 64 x LP (fp32 W / tf32 P)

    const int b   = blockIdx.y;
    const int sp  = blockIdx.z;
    const int q0  = blockIdx.x * BM;
    const int kvb = sp * KVLEN;
    const int tid = threadIdx.x, lane = tid & 31, warp = tid >> 5;
    const int gid = lane >> 2, tig = lane & 3;
    const int rw  = warp * 16;

    const uint32_t* qb  = g_qkv[0] + (size_t)b * N_ * FO_;
    const uint32_t* kb  = g_qkv[1] + (size_t)b * N_ * FO_;
    const uint32_t* vtb = g_qkv[2] + (size_t)b * FO_ * N_;   // [feat][tok]
    const float*    wb  = xw + (size_t)b * N_ * N_;

    const uint32_t KsA0 = (uint32_t)__cvta_generic_to_shared(KsB);
    const uint32_t VsA0 = (uint32_t)__cvta_generic_to_shared(VsB);
    const uint32_t WsA0 = (uint32_t)__cvta_generic_to_shared(WsB);

    // ldmatrix lane mapping (rows = n-dim, cols = k-dim)
    const int row_  = ((lane >> 4) << 3) + (lane & 7);
    const int half_ = ((lane >> 3) & 1) << 2;
    // P A-frags
    const int arow  = rw + (((lane >> 3) & 1) << 3) + (lane & 7);
    const int acol  = ((lane >> 4) << 2);

    // ---- stage Q (64 x 64) through the K double-buffer ----
    {
        const uint4* q4 = (const uint4*)(qb + (size_t)q0 * FO_);
        for (int i = tid; i < BM * (FO_ / 4); i += 128) {
            uint4 v = q4[i];
            uint32_t* d = KsB + (i >> 4) * LK + ((i & 15) << 2);
            d[0] = v.x; d[1] = v.y; d[2] = v.z; d[3] = v.w;
        }
    }
    __syncthreads();
    uint32_t Qa[8][4];
#pragma unroll
    for (int kc = 0; kc < 8; kc++) {
        const uint32_t* Ar = KsB + (rw + gid) * LK + kc * 8 + tig;
        Qa[kc][0] = Ar[0]; Qa[kc][2] = Ar[4];
        Qa[kc][1] = Ar[8 * LK]; Qa[kc][3] = Ar[8 * LK + 4];
    }
    __syncthreads();

    auto issue_loads = [&](int it, int buf) {
        const int kv0 = kvb + it * BN;
        uint32_t kbase = KsA0 + (uint32_t)(buf * BN * LK * 4);
        uint32_t vbase = VsA0 + (uint32_t)(buf * 64 * LVT * 4);
        uint32_t wbase = WsA0 + (uint32_t)(buf * BM * LP * 4);
        const uint32_t* ksrc = kb + (size_t)kv0 * FO_;
        const uint32_t* vsrc = vtb + kv0;                    // row stride N_
        const float*    wsrc = wb + (size_t)q0 * N_ + kv0;
#pragma unroll
        for (int j = 0; j < 4; j++) {              // 512 16B chunks per array
            int i = tid + 128 * j;
            {   // K: 32 rows x 16 chunks
                int r = i >> 4, c = (i & 15) << 2;
                cp16(kbase + (uint32_t)((r * LK + c) * 4), ksrc + r * FO_ + c);
            }
            {   // Vt: 64 rows x 8 chunks
                int r = i >> 3, c = (i & 7) << 2;
                cp16(vbase + (uint32_t)((r * LVT + c) * 4), vsrc + (size_t)r * N_ + c);
            }
            {   // W: 64 rows x 8 chunks
                int r = i >> 3, c = (i & 7) << 2;
                cp16(wbase + (uint32_t)((r * LP + c) * 4), wsrc + (size_t)r * N_ + c);
            }
        }
    };

    float Oc[8][4];
#pragma unroll
    for (int nt = 0; nt < 8; nt++) { Oc[nt][0] = Oc[nt][1] = Oc[nt][2] = Oc[nt][3] = 0.f; }
    float l0 = 0.f, l1 = 0.f;   // per-thread partial row sums (2^-32-scaled)

    issue_loads(0, 0);
    cp_commit();

    for (int it = 0; it < NIT; it++) {
        const int buf = it & 1;
        cp_wait0();
        __syncthreads();   // chunks arrived; all warps finished iter it-1

        // prefetch next tiles NOW: buf^1 is provably consumed (barrier above)
        if (it + 1 < NIT) { issue_loads(it + 1, buf ^ 1); cp_commit(); }

        const uint32_t KsA = KsA0 + (uint32_t)(buf * BN * LK * 4);
        const uint32_t VsA = VsA0 + (uint32_t)(buf * 64 * LVT * 4);
        uint32_t*       Wp = WsB + buf * BM * LP;    // W tile, becomes P tile
        const uint32_t  WpA = WsA0 + (uint32_t)(buf * BM * LP * 4);
        const float*    Wf = (const float*)Wp;

        // ---- S = Q @ K^T : 16 rows x 32 cols, kc over 8 feat chunks ----
        float S[4][4];
#pragma unroll
        for (int nt = 0; nt < 4; nt++) { S[nt][0] = S[nt][1] = S[nt][2] = S[nt][3] = 0.f; }
#pragma unroll
        for (int kc = 0; kc < 8; kc++) {
            uint32_t bk[2][4];
#pragma unroll
            for (int ntp = 0; ntp < 2; ntp++)
                ldsm4(bk[ntp][0], bk[ntp][1], bk[ntp][2], bk[ntp][3],
                      KsA + (uint32_t)((((ntp * 16 + row_) * LK) + kc * 8 + half_) * 4));
#pragma unroll
            for (int ntp = 0; ntp < 2; ntp++) {
                mma8(S[2 * ntp],     Qa[kc], bk[ntp][0], bk[ntp][1]);
                mma8(S[2 * ntp + 1], Qa[kc], bk[ntp][2], bk[ntp][3]);
            }
        }

        // ---- * x_weight, relu, p = 2^(max(s*w-32, -32)) : FFMA-folded ----
#pragma unroll
        for (int nt = 0; nt < 4; nt++) {
            const float2 wA = *(const float2*)(Wf + (rw + gid) * LP + nt * 8 + 2 * tig);
            const float2 wB = *(const float2*)(Wf + (rw + gid + 8) * LP + nt * 8 + 2 * tig);
            float p0 = ex2(fmaxf(fmaf(S[nt][0], wA.x, -32.f), -32.f));
            float p1 = ex2(fmaxf(fmaf(S[nt][1], wA.y, -32.f), -32.f));
            float p2 = ex2(fmaxf(fmaf(S[nt][2], wB.x, -32.f), -32.f));
            float p3 = ex2(fmaxf(fmaf(S[nt][3], wB.y, -32.f), -32.f));
            l0 += p0 + p1; l1 += p2 + p3;
            *(uint2*)(Wp + (rw + gid) * LP + nt * 8 + 2 * tig) =
                make_uint2(f2tf(p0), f2tf(p1));
            *(uint2*)(Wp + (rw + gid + 8) * LP + nt * 8 + 2 * tig) =
                make_uint2(f2tf(p2), f2tf(p3));
        }
        __syncwarp();   // P rows (warp-private) visible to ldmatrix gathers

        // ---- O += P @ V : kc over 4 tok chunks, 8 feat n-tiles ----
#pragma unroll
        for (int kc = 0; kc < 4; kc++) {
            uint32_t a[4];
            ldsm4(a[0], a[1], a[2], a[3],
                  WpA + (uint32_t)(((arow * LP) + kc * 8 + acol) * 4));
            uint32_t bv[4][4];
#pragma unroll
            for (int ntp = 0; ntp < 4; ntp++)
                ldsm4(bv[ntp][0], bv[ntp][1], bv[ntp][2], bv[ntp][3],
                      VsA + (uint32_t)((((ntp * 16 + row_) * LVT) + kc * 8 + half_) * 4));
#pragma unroll
            for (int ntp = 0; ntp < 4; ntp++) {
                mma8(Oc[2 * ntp],     a, bv[ntp][0], bv[ntp][1]);
                mma8(Oc[2 * ntp + 1], a, bv[ntp][2], bv[ntp][3]);
            }
        }
    }

    // ---- final l reduction across the quad, store partials ----
    l0 += __shfl_xor_sync(0xffffffffu, l0, 1);
    l0 += __shfl_xor_sync(0xffffffffu, l0, 2);
    l1 += __shfl_xor_sync(0xffffffffu, l1, 1);
    l1 += __shfl_xor_sync(0xffffffffu, l1, 2);

    float* pO = g_pO + ((size_t)(sp * B_ + b) * N_ + q0) * FO_;
#pragma unroll
    for (int nt = 0; nt < 8; nt++) {
        int col = nt * 8 + 2 * tig;
        *(float2*)(pO + (size_t)(rw + gid) * FO_ + col) =
            make_float2(Oc[nt][0], Oc[nt][1]);
        *(float2*)(pO + (size_t)(rw + gid + 8) * FO_ + col) =
            make_float2(Oc[nt][2], Oc[nt][3]);
    }
    if (tig == 0) {
        int idx = (sp * B_ + b) * N_ + q0 + rw + gid;
        g_pL[idx] = l0;
        g_pL[idx + 8] = l1;
    }
}

// ---------------------------------------------------------------------------
// Kernel 3: merge the 4 split-KV partials (common scale), normalize, relu
// ---------------------------------------------------------------------------
__global__ void __launch_bounds__(256)
combine_kernel(float* __restrict__ out)
{
    const int idx = blockIdx.x * 256 + threadIdx.x;   // B_*N_*16 float4 slots
    const int row = idx >> 4;
    const int c4  = (idx & 15) << 2;

    float lsum = 0.f;
#pragma unroll
    for (int s = 0; s < SPLITS; s++) lsum += g_pL[s * B_ * N_ + row];
    const float inv = 1.f / lsum;

    float4 acc = make_float4(0.f, 0.f, 0.f, 0.f);
#pragma unroll
    for (int s = 0; s < SPLITS; s++) {
        const float4 o = *(const float4*)(g_pO + ((size_t)s * B_ * N_ + row) * FO_ + c4);
        acc.x += o.x; acc.y += o.y; acc.z += o.z; acc.w += o.w;
    }
    float4 r;
    r.x = fmaxf(acc.x * inv, 0.f);
    r.y = fmaxf(acc.y * inv, 0.f);
    r.z = fmaxf(acc.z * inv, 0.f);
    r.w = fmaxf(acc.w * inv, 0.f);
    *(float4*)(out + (size_t)row * FO_ + c4) = r;
}

// ---------------------------------------------------------------------------
extern "C" void kernel_launch(void* const* d_in, const int* in_sizes, int n_in,
                              void* d_out, int out_size)
{
    const float* feature = (const float*)d_in[0];
    const float* xw      = (const float*)d_in[1];
    const float* W11 = (const float*)d_in[2],  *b11 = (const float*)d_in[3];
    const float* W12 = (const float*)d_in[4],  *b12 = (const float*)d_in[5];
    const float* W21 = (const float*)d_in[6],  *b21 = (const float*)d_in[7];
    const float* W22 = (const float*)d_in[8],  *b22 = (const float*)d_in[9];
    const float* W31 = (const float*)d_in[10], *b31 = (const float*)d_in[11];
    const float* W32 = (const float*)d_in[12], *b32 = (const float*)d_in[13];

    const int mlp_smem  = (64 * LX + 128 * LW + 64 * LW) * 4;               // 90112
    const int attn_smem = (2 * BN * LK + 2 * 64 * LVT + 2 * BM * LP) * 4;   // 54272
    cudaFuncSetAttribute(mlp_kernel,  cudaFuncAttributeMaxDynamicSharedMemorySize, mlp_smem);
    cudaFuncSetAttribute(attn_kernel, cudaFuncAttributeMaxDynamicSharedMemorySize, attn_smem);

    mlp_kernel<<<dim3((B_ * N_) / 64, 3), 128, mlp_smem>>>(
        feature, W11, b11, W12, b12, W21, b21, W22, b22, W31, b31, W32, b32);

    attn_kernel<<<dim3(N_ / BM, B_, SPLITS), 128, attn_smem>>>(xw);

    combine_kernel<<<(B_ * N_ * 16) / 256, 256>>>((float*)d_out);
}